// round 15
// baseline (speedup 1.0000x reference)
#include <cuda_runtime.h>
#include <cuda_bf16.h>
#include <cuda_fp16.h>
#include <math.h>
#include <stdint.h>

#define NN   50000
#define HID  128
#define RR   8
#define EE   640000
#define EE2  200000
#define NCLS 8

// ---------------- scratch (device globals; allocation-free) ----------------
__device__ __half g_xw[NN * RR * HID];
__device__ float g_aq[NN * RR * 4];
__device__ float g_ak[NN * RR * 4];
__device__ __half g_x16[NN * HID], g_h116[NN * HID];
__device__ __nv_bfloat16 g_xhi[NN * HID],  g_xlo[NN * HID];
__device__ __nv_bfloat16 g_h1hi[NN * HID], g_h1lo[NN * HID];
__device__ __nv_bfloat16 g_hshi[NN * HID], g_hslo[NN * HID];
__device__ __half g_w16[2 * RR * HID * HID];                     // [layer][r][k][n]
__device__ __nv_bfloat16 g_m1hi[2 * HID * HID], g_m1lo[2 * HID * HID]; // [k=256][n=128]
__device__ __nv_bfloat16 g_qkhi[2][64 * HID], g_qklo[2][64 * HID];
__device__ float g_uv[NN * 256];           // [node][u:0-127 | v:128-255]
__device__ int g_deg[NN], g_rowptr[NN + 1], g_cursor[NN], g_csr[EE];

// ---------------- helpers ----------------
__device__ __forceinline__ void bsplit(float v, __nv_bfloat16& hi, __nv_bfloat16& lo) {
    hi = __float2bfloat16(v);
    lo = __float2bfloat16(v - __bfloat162float(hi));
}
__device__ __forceinline__ void mma_bf16(float4& d, const uint32_t* a, const uint32_t* b) {
    asm volatile(
        "mma.sync.aligned.m16n8k16.row.col.f32.bf16.bf16.f32 "
        "{%0,%1,%2,%3}, {%4,%5,%6,%7}, {%8,%9}, {%0,%1,%2,%3};"
        : "+f"(d.x), "+f"(d.y), "+f"(d.z), "+f"(d.w)
        : "r"(a[0]), "r"(a[1]), "r"(a[2]), "r"(a[3]), "r"(b[0]), "r"(b[1]));
}
__device__ __forceinline__ void mma_f16(float4& d, const uint32_t* a, const uint32_t* b) {
    asm volatile(
        "mma.sync.aligned.m16n8k16.row.col.f32.f16.f16.f32 "
        "{%0,%1,%2,%3}, {%4,%5,%6,%7}, {%8,%9}, {%0,%1,%2,%3};"
        : "+f"(d.x), "+f"(d.y), "+f"(d.z), "+f"(d.w)
        : "r"(a[0]), "r"(a[1]), "r"(a[2]), "r"(a[3]), "r"(b[0]), "r"(b[1]));
}
__device__ __forceinline__ void ldm_x4(uint32_t* r, const void* p) {
    uint32_t a = (uint32_t)__cvta_generic_to_shared(p);
    asm volatile("ldmatrix.sync.aligned.m8n8.x4.shared.b16 {%0,%1,%2,%3}, [%4];"
                 : "=r"(r[0]), "=r"(r[1]), "=r"(r[2]), "=r"(r[3]) : "r"(a));
}
__device__ __forceinline__ void ldm_x4_t(uint32_t* r, const void* p) {
    uint32_t a = (uint32_t)__cvta_generic_to_shared(p);
    asm volatile("ldmatrix.sync.aligned.m8n8.x4.trans.shared.b16 {%0,%1,%2,%3}, [%4];"
                 : "=r"(r[0]), "=r"(r[1]), "=r"(r[2]), "=r"(r[3]) : "r"(a));
}
__device__ __forceinline__ void cpa(uint32_t d, const void* s) {
    asm volatile("cp.async.cg.shared.global [%0], [%1], 16;" :: "r"(d), "l"(s));
}
__device__ __forceinline__ void cp_commit() { asm volatile("cp.async.commit_group;"); }
__device__ __forceinline__ void cp_wait0() { asm volatile("cp.async.wait_group 0;"); }
__device__ __forceinline__ void cp_wait1() { asm volatile("cp.async.wait_group 1;"); }

#define STAGE_BYTES 37888   // uv stage: Ah 0, Al 10240, Bh 20480, Bl 29184
#define G_STAGE 18944       // fp16 gemm stage: A 0 (10240), B 10240 (8704)

// ---------------- CSR build ----------------
__global__ void k_zero() {
    int i = blockIdx.x * blockDim.x + threadIdx.x;
    if (i < NN) g_deg[i] = 0;
}
__global__ void k_hist(const int* __restrict__ ei) {
    int e = blockIdx.x * blockDim.x + threadIdx.x;
    if (e < EE) atomicAdd(&g_deg[ei[EE + e]], 1);
}
__global__ void k_scan() {
    __shared__ int sp[1024];
    const int t = threadIdx.x;
    const int chunk = (NN + 1023) / 1024;
    int start = t * chunk, end = min(start + chunk, NN);
    int s = 0;
    for (int i = start; i < end; i++) s += g_deg[i];
    sp[t] = s;
    __syncthreads();
    for (int off = 1; off < 1024; off <<= 1) {
        int v = (t >= off) ? sp[t - off] : 0;
        __syncthreads();
        sp[t] += v;
        __syncthreads();
    }
    int run = (t == 0) ? 0 : sp[t - 1];
    for (int i = start; i < end; i++) {
        g_rowptr[i] = run;
        g_cursor[i] = run;
        run += g_deg[i];
    }
    if (t == 1023) g_rowptr[NN] = run;
}
__global__ void k_fill(const int* __restrict__ ei, const int* __restrict__ et) {
    int e = blockIdx.x * blockDim.x + threadIdx.x;
    if (e >= EE) return;
    int dst = ei[EE + e];
    int pos = atomicAdd(&g_cursor[dst], 1);
    g_csr[pos] = ei[e] * 8 + et[e];
}

// ---------------- fused prep ----------------
__global__ void k_prep(const float* __restrict__ x, const float* __restrict__ w1,
                       const float* __restrict__ w2, const float* __restrict__ mw1) {
    const int R0 = NN * HID / 4;
    const int R1 = RR * HID * HID / 4;
    const int R3 = 2 * HID * HID / 4;
    int id = blockIdx.x * blockDim.x + threadIdx.x;
    if (id < R0) {
        float4 v = ((const float4*)x)[id];
        union { __nv_bfloat16 b[4]; uint2 u; } ph, pl;
        bsplit(v.x, ph.b[0], pl.b[0]); bsplit(v.y, ph.b[1], pl.b[1]);
        bsplit(v.z, ph.b[2], pl.b[2]); bsplit(v.w, ph.b[3], pl.b[3]);
        *(uint2*)&g_xhi[id * 4] = ph.u;
        *(uint2*)&g_xlo[id * 4] = pl.u;
        __half2 h0 = __floats2half2_rn(v.x, v.y);
        __half2 h1 = __floats2half2_rn(v.z, v.w);
        uint2 u16;
        u16.x = *(uint32_t*)&h0; u16.y = *(uint32_t*)&h1;
        *(uint2*)&g_x16[id * 4] = u16;
    } else if (id < R0 + 2 * R1) {
        int layer = (id - R0) >= R1;
        int off = id - R0 - layer * R1;
        const float* src = layer ? w2 : w1;
        float4 v = ((const float4*)src)[off];
        __half2 h0 = __floats2half2_rn(v.x, v.y);
        __half2 h1 = __floats2half2_rn(v.z, v.w);
        uint2 u16;
        u16.x = *(uint32_t*)&h0; u16.y = *(uint32_t*)&h1;
        *(uint2*)&g_w16[layer * RR * HID * HID + off * 4] = u16;
    } else if (id < R0 + 2 * R1 + R3) {
        int off = id - R0 - 2 * R1;
        float4 v = ((const float4*)mw1)[off];
        union { __nv_bfloat16 b[4]; uint2 u; } ph, pl;
        bsplit(v.x, ph.b[0], pl.b[0]); bsplit(v.y, ph.b[1], pl.b[1]);
        bsplit(v.z, ph.b[2], pl.b[2]); bsplit(v.w, ph.b[3], pl.b[3]);
        *(uint2*)&g_m1hi[off * 4] = ph.u;
        *(uint2*)&g_m1lo[off * 4] = pl.u;
    }
}

// ---------------- Wqk planes ----------------
__global__ void k_wqk(const float* __restrict__ W, const float* __restrict__ q,
                      const float* __restrict__ kk, int layer) {
    int id = blockIdx.x * blockDim.x + threadIdx.x;
    if (id >= 64 * HID) return;
    int i = id & 127, n = id >> 7;
    int h = n & 3, r = (n >> 2) & 7;
    const float* vq = (n < 32) ? q : kk;
    const float* wrow = W + r * HID * HID + i * HID;
    float s = 0.f;
#pragma unroll 4
    for (int o = 0; o < HID; o++) s += wrow[o] * vq[o * 4 + h];
    bsplit(s, g_qkhi[layer][n * HID + i], g_qklo[layer][n * HID + i]);
}

// ---------------- fp16 single-plane GEMM (cp.async pipelined): xw = A @ W[layer][r] ----------------
__global__ void __launch_bounds__(256, 2)
k_gemm16(int layer) {
    extern __shared__ char smem[];
    const int t = threadIdx.x, lane = t & 31, wid = t >> 5;
    const int wm = wid & 3, wn = wid >> 2, g = lane >> 2, tg = lane & 3;
    const int r = blockIdx.y, row0 = blockIdx.x * 128;
    const __half* A = layer ? g_h116 : g_x16;
    const __half* B = g_w16 + (layer * RR + r) * HID * HID;

    const int lr = t >> 1, lc = (t & 1) * 16;
    const int garow = row0 + lr;
    const __half* asrc = (garow < NN ? A + garow * 128 : A) + lc;
    const int bk = t >> 3, bn = (t & 7) * 16;

    uint32_t sbase = (uint32_t)__cvta_generic_to_shared(smem);
    uint32_t a_d[2], b_d[2];
#pragma unroll
    for (int s = 0; s < 2; s++) {
        uint32_t sb = sbase + s * G_STAGE;
        a_d[s] = sb + (lr * 40 + lc) * 2;
        b_d[s] = sb + 10240 + (bk * 136 + bn) * 2;
    }
    auto issue = [&](int k0, int s) {
        cpa(a_d[s], asrc + k0);  cpa(a_d[s] + 16, asrc + k0 + 8);
        const __half* bp = B + (k0 + bk) * 128 + bn;
        cpa(b_d[s], bp);         cpa(b_d[s] + 16, bp + 8);
        cp_commit();
    };

    float4 acc[2][8];
#pragma unroll
    for (int i = 0; i < 2; i++)
#pragma unroll
        for (int j = 0; j < 8; j++) acc[i][j] = make_float4(0.f, 0.f, 0.f, 0.f);

    const int a_row = lane & 15, a_col = ((lane >> 4) & 1) * 8;
    const int b_k = (lane & 7) + ((lane & 8) ? 8 : 0);
    const int b_n8 = (lane & 16) ? 8 : 0;

    issue(0, 0);
    for (int it = 0; it < 4; it++) {
        if (it < 3) { issue((it + 1) * 32, (it + 1) & 1); cp_wait1(); }
        else cp_wait0();
        __syncthreads();
        char* st = smem + (it & 1) * G_STAGE;
        __half (*Ah)[40]  = (__half(*)[40])(st);
        __half (*Bh)[136] = (__half(*)[136])(st + 10240);
#pragma unroll
        for (int ks = 0; ks < 32; ks += 16) {
            uint32_t af[2][4];
#pragma unroll
            for (int i = 0; i < 2; i++)
                ldm_x4(af[i], &Ah[wm * 32 + i * 16 + a_row][ks + a_col]);
            uint32_t bf[8][2];
#pragma unroll
            for (int jj = 0; jj < 4; jj++) {
                uint32_t rh[4];
                ldm_x4_t(rh, &Bh[ks + b_k][wn * 64 + jj * 16 + b_n8]);
                bf[2 * jj][0] = rh[0]; bf[2 * jj][1] = rh[1];
                bf[2 * jj + 1][0] = rh[2]; bf[2 * jj + 1][1] = rh[3];
            }
#pragma unroll
            for (int i = 0; i < 2; i++)
#pragma unroll
                for (int j = 0; j < 8; j++)
                    mma_f16(acc[i][j], af[i], bf[j]);
        }
        __syncthreads();
    }

#pragma unroll
    for (int i = 0; i < 2; i++)
#pragma unroll
        for (int half = 0; half < 2; half++) {
            int gr = row0 + wm * 32 + i * 16 + half * 8 + g;
            if (gr < NN) {
                __half* dst = &g_xw[(gr * 8 + r) * 128 + wn * 64 + 2 * tg];
#pragma unroll
                for (int j = 0; j < 8; j++) {
                    float2 v = half ? make_float2(acc[i][j].z, acc[i][j].w)
                                    : make_float2(acc[i][j].x, acc[i][j].y);
                    *(__half2*)(dst + j * 8) = __floats2half2_rn(v.x, v.y);
                }
            }
        }
}

// ---------------- aq/ak GEMM (bf16x3; unchanged) ----------------
__global__ void __launch_bounds__(256)
k_aqk(int layer) {
    __shared__ __nv_bfloat16 Ah[128][40], Al[128][40], Bh[64][40], Bl[64][40];
    const int t = threadIdx.x, lane = t & 31, wid = t >> 5;
    const int wm = wid & 3, wn = wid >> 2, g = lane >> 2, tg = lane & 3;
    const int row0 = blockIdx.x * 128;
    const __nv_bfloat16* Ahi = layer ? g_h1hi : g_xhi;
    const __nv_bfloat16* Alo = layer ? g_h1lo : g_xlo;
    const __nv_bfloat16* Bhi = g_qkhi[layer];
    const __nv_bfloat16* Blo = g_qklo[layer];

    const int lr = t >> 1, lc = (t & 1) * 16;
    const int garow = row0 + lr;
    const __nv_bfloat16* ahp = (garow < NN ? Ahi + garow * 128 : Ahi) + lc;
    const __nv_bfloat16* alp = (garow < NN ? Alo + garow * 128 : Alo) + lc;
    const int br = t >> 2, bc = (t & 3) * 8;

    float4 acc[2][4];
#pragma unroll
    for (int i = 0; i < 2; i++)
#pragma unroll
        for (int j = 0; j < 4; j++) acc[i][j] = make_float4(0.f, 0.f, 0.f, 0.f);

    const int a_row = lane & 15, a_col = ((lane >> 4) & 1) * 8;
    const int b_row = (lane & 7) + ((lane & 16) ? 8 : 0);
    const int b_col = (lane & 8) ? 8 : 0;

    for (int k0 = 0; k0 < 128; k0 += 32) {
        uint4 a0 = *(const uint4*)(ahp + k0);
        uint4 a1 = *(const uint4*)(ahp + k0 + 8);
        uint4 a2 = *(const uint4*)(alp + k0);
        uint4 a3 = *(const uint4*)(alp + k0 + 8);
        uint4 b0 = *(const uint4*)&Bhi[br * 128 + k0 + bc];
        uint4 b1 = *(const uint4*)&Blo[br * 128 + k0 + bc];
        __syncthreads();
        *(uint4*)&Ah[lr][lc] = a0; *(uint4*)&Ah[lr][lc + 8] = a1;
        *(uint4*)&Al[lr][lc] = a2; *(uint4*)&Al[lr][lc + 8] = a3;
        *(uint4*)&Bh[br][bc] = b0;
        *(uint4*)&Bl[br][bc] = b1;
        __syncthreads();
#pragma unroll
        for (int ks = 0; ks < 32; ks += 16) {
            uint32_t ahh[2][4], all[2][4];
#pragma unroll
            for (int i = 0; i < 2; i++) {
                ldm_x4(ahh[i], &Ah[wm * 32 + i * 16 + a_row][ks + a_col]);
                ldm_x4(all[i], &Al[wm * 32 + i * 16 + a_row][ks + a_col]);
            }
            uint32_t bhh[4][2], bll[4][2];
#pragma unroll
            for (int jj = 0; jj < 2; jj++) {
                uint32_t rh[4], rl[4];
                ldm_x4(rh, &Bh[wn * 32 + jj * 16 + b_row][ks + b_col]);
                ldm_x4(rl, &Bl[wn * 32 + jj * 16 + b_row][ks + b_col]);
                bhh[2 * jj][0] = rh[0]; bhh[2 * jj][1] = rh[1];
                bhh[2 * jj + 1][0] = rh[2]; bhh[2 * jj + 1][1] = rh[3];
                bll[2 * jj][0] = rl[0]; bll[2 * jj][1] = rl[1];
                bll[2 * jj + 1][0] = rl[2]; bll[2 * jj + 1][1] = rl[3];
            }
#pragma unroll
            for (int i = 0; i < 2; i++)
#pragma unroll
                for (int j = 0; j < 4; j++) {
                    mma_bf16(acc[i][j], ahh[i], bll[j]);
                    mma_bf16(acc[i][j], all[i], bhh[j]);
                    mma_bf16(acc[i][j], ahh[i], bhh[j]);
                }
        }
    }

#pragma unroll
    for (int i = 0; i < 2; i++)
#pragma unroll
        for (int half = 0; half < 2; half++) {
            int gr = row0 + wm * 32 + i * 16 + half * 8 + g;
            if (gr >= NN) continue;
#pragma unroll
            for (int j = 0; j < 4; j++) {
                int col = wn * 32 + j * 8 + 2 * tg;
                float2 v = half ? make_float2(acc[i][j].z, acc[i][j].w)
                                : make_float2(acc[i][j].x, acc[i][j].y);
                if (col < 32) *(float2*)&g_aq[gr * 32 + col] = v;
                else          *(float2*)&g_ak[gr * 32 + col - 32] = v;
            }
        }
}

// ---------------- fused per-node softmax + aggregate + bias + relu + LN ----------------
__global__ void k_agg_ln(const float* __restrict__ bias, const float* __restrict__ gam,
                         const float* __restrict__ bet, int layer) {
    int nid = blockIdx.x * 8 + (threadIdx.x >> 5);
    if (nid >= NN) return;
    int lane = threadIdx.x & 31;
    int h = lane >> 3;
    int e8 = lane & 7;
    int j0 = g_rowptr[nid], j1 = g_rowptr[nid + 1];
    float aqr = g_aq[nid * 32 + lane];
    float4 num = make_float4(0.f, 0.f, 0.f, 0.f);
    float den = 0.f;

    int base = j0;
    for (; base + 8 <= j1; base += 8) {
        int p = g_csr[base + e8];
        int rr = p & 7;
        float aqv = __shfl_sync(0xffffffffu, aqr, rr * 4 + h);
        float a = aqv + g_ak[p * 4 + h];
        a = a > 0.f ? a : 0.2f * a;
        float ex = __expf(a);
        den += ex;
        uint2 rbuf[8];
#pragma unroll
        for (int e = 0; e < 8; e++) {
            int pe = __shfl_sync(0xffffffffu, p, e);
            rbuf[e] = *(const uint2*)&g_xw[pe * 128 + lane * 4];
        }
#pragma unroll
        for (int e = 0; e < 8; e++) {
            float exe = __shfl_sync(0xffffffffu, ex, (lane & 24) + e);
            float2 f0 = __half22float2(*(__half2*)&rbuf[e].x);
            float2 f1 = __half22float2(*(__half2*)&rbuf[e].y);
            num.x += exe * f0.x; num.y += exe * f0.y;
            num.z += exe * f1.x; num.w += exe * f1.y;
        }
    }
    if (base < j1) {
        int idx = base + e8;
        bool ok = idx < j1;
        int p = ok ? g_csr[idx] : 0;
        int rr = p & 7;
        float aqv = __shfl_sync(0xffffffffu, aqr, rr * 4 + h);
        float ex = 0.f;
        if (ok) {
            float a = aqv + g_ak[p * 4 + h];
            a = a > 0.f ? a : 0.2f * a;
            ex = __expf(a);
        }
        den += ex;
        int cnt = j1 - base;
        for (int e = 0; e < cnt; e++) {
            float exe = __shfl_sync(0xffffffffu, ex, (lane & 24) + e);
            int pe = __shfl_sync(0xffffffffu, p, e);
            uint2 raw = *(const uint2*)&g_xw[pe * 128 + lane * 4];
            float2 f0 = __half22float2(*(__half2*)&raw.x);
            float2 f1 = __half22float2(*(__half2*)&raw.y);
            num.x += exe * f0.x; num.y += exe * f0.y;
            num.z += exe * f1.x; num.w += exe * f1.y;
        }
    }

    den += __shfl_xor_sync(0xffffffffu, den, 1);
    den += __shfl_xor_sync(0xffffffffu, den, 2);
    den += __shfl_xor_sync(0xffffffffu, den, 4);
    float inv = 1.f / (den + 1e-16f);
    float4 bb = *(const float4*)&bias[lane * 4];
    float4 v;
    v.x = fmaxf(num.x * inv + bb.x, 0.f);
    v.y = fmaxf(num.y * inv + bb.y, 0.f);
    v.z = fmaxf(num.z * inv + bb.z, 0.f);
    v.w = fmaxf(num.w * inv + bb.w, 0.f);
    float s = v.x + v.y + v.z + v.w;
#pragma unroll
    for (int o = 16; o >= 1; o >>= 1) s += __shfl_xor_sync(0xffffffffu, s, o);
    float mean = s * (1.f / 128.f);
    float dx = v.x - mean, dy = v.y - mean, dz = v.z - mean, dw = v.w - mean;
    float ss = dx * dx + dy * dy + dz * dz + dw * dw;
#pragma unroll
    for (int o = 16; o >= 1; o >>= 1) ss += __shfl_xor_sync(0xffffffffu, ss, o);
    float rs = rsqrtf(ss * (1.f / 128.f) + 1e-5f);
    float4 g4 = *(const float4*)&gam[lane * 4];
    float4 b4 = *(const float4*)&bet[lane * 4];
    float4 y;
    y.x = dx * rs * g4.x + b4.x;
    y.y = dy * rs * g4.y + b4.y;
    y.z = dz * rs * g4.z + b4.z;
    y.w = dw * rs * g4.w + b4.w;
    union { __nv_bfloat16 b[4]; uint2 u; } ph, pl;
    if (layer == 1) {
        bsplit(y.x, ph.b[0], pl.b[0]); bsplit(y.y, ph.b[1], pl.b[1]);
        bsplit(y.z, ph.b[2], pl.b[2]); bsplit(y.w, ph.b[3], pl.b[3]);
        *(uint2*)&g_h1hi[nid * HID + lane * 4] = ph.u;
        *(uint2*)&g_h1lo[nid * HID + lane * 4] = pl.u;
        __half2 h0 = __floats2half2_rn(y.x, y.y);
        __half2 h1 = __floats2half2_rn(y.z, y.w);
        uint2 u16;
        u16.x = *(uint32_t*)&h0; u16.y = *(uint32_t*)&h1;
        *(uint2*)&g_h116[nid * HID + lane * 4] = u16;
    } else {
        uint2 rh = *(const uint2*)&g_h1hi[nid * HID + lane * 4];
        uint2 rl = *(const uint2*)&g_h1lo[nid * HID + lane * 4];
        const __nv_bfloat16* hb = (const __nv_bfloat16*)&rh;
        const __nv_bfloat16* lb = (const __nv_bfloat16*)&rl;
        y.x += __bfloat162float(hb[0]) + __bfloat162float(lb[0]);
        y.y += __bfloat162float(hb[1]) + __bfloat162float(lb[1]);
        y.z += __bfloat162float(hb[2]) + __bfloat162float(lb[2]);
        y.w += __bfloat162float(hb[3]) + __bfloat162float(lb[3]);
        bsplit(y.x, ph.b[0], pl.b[0]); bsplit(y.y, ph.b[1], pl.b[1]);
        bsplit(y.z, ph.b[2], pl.b[2]); bsplit(y.w, ph.b[3], pl.b[3]);
        *(uint2*)&g_hshi[nid * HID + lane * 4] = ph.u;
        *(uint2*)&g_hslo[nid * HID + lane * 4] = pl.u;
    }
}

// ---------------- u/v GEMM (bf16x3): u = hs @ mw1_top, v = hs @ mw1_bot ----------------
// grid (ceil(NN/128), 2); blockIdx.y: 0 -> u (mw1 rows 0-127), 1 -> v (rows 128-255)
__global__ void __launch_bounds__(256, 2)
k_uv() {
    extern __shared__ char smem[];
    const int t = threadIdx.x, lane = t & 31, wid = t >> 5;
    const int wm = wid & 3, wn = wid >> 2, g = lane >> 2, tg = lane & 3;
    const int row0 = blockIdx.x * 128;
    const int halfsel = blockIdx.y;

    const int lr = t >> 1, lc = (t & 1) * 16;
    const int garow = row0 + lr;
    const __nv_bfloat16* ah_src = (garow < NN ? g_hshi + garow * 128 : g_hshi) + lc;
    const __nv_bfloat16* al_src = (garow < NN ? g_hslo + garow * 128 : g_hslo) + lc;
    const int bk = t >> 3, bn = (t & 7) * 16;

    uint32_t sbase = (uint32_t)__cvta_generic_to_shared(smem);
    uint32_t ah_d[2], al_d[2], bh_d[2], bl_d[2];
#pragma unroll
    for (int s = 0; s < 2; s++) {
        uint32_t sb2 = sbase + s * STAGE_BYTES;
        ah_d[s] = sb2 + (lr * 40 + lc) * 2;
        al_d[s] = sb2 + 10240 + (lr * 40 + lc) * 2;
        bh_d[s] = sb2 + 20480 + (bk * 136 + bn) * 2;
        bl_d[s] = sb2 + 29184 + (bk * 136 + bn) * 2;
    }
    auto issue = [&](int k0, int s) {
        cpa(ah_d[s], ah_src + k0);  cpa(ah_d[s] + 16, ah_src + k0 + 8);
        cpa(al_d[s], al_src + k0);  cpa(al_d[s] + 16, al_src + k0 + 8);
        const __nv_bfloat16* bh = &g_m1hi[(halfsel * 128 + k0 + bk) * 128 + bn];
        const __nv_bfloat16* bl = &g_m1lo[(halfsel * 128 + k0 + bk) * 128 + bn];
        cpa(bh_d[s], bh);  cpa(bh_d[s] + 16, bh + 8);
        cpa(bl_d[s], bl);  cpa(bl_d[s] + 16, bl + 8);
        cp_commit();
    };

    float4 acc[2][8];
#pragma unroll
    for (int i = 0; i < 2; i++)
#pragma unroll
        for (int j = 0; j < 8; j++) acc[i][j] = make_float4(0.f, 0.f, 0.f, 0.f);

    const int a_row = lane & 15, a_col = ((lane >> 4) & 1) * 8;
    const int b_k = (lane & 7) + ((lane & 8) ? 8 : 0);
    const int b_n8 = (lane & 16) ? 8 : 0;

    issue(0, 0);
    for (int it = 0; it < 4; it++) {
        if (it < 3) { issue((it + 1) * 32, (it + 1) & 1); cp_wait1(); }
        else cp_wait0();
        __syncthreads();
        char* st = smem + (it & 1) * STAGE_BYTES;
        __nv_bfloat16 (*Ah)[40]  = (__nv_bfloat16(*)[40])(st);
        __nv_bfloat16 (*Al)[40]  = (__nv_bfloat16(*)[40])(st + 10240);
        __nv_bfloat16 (*Bh)[136] = (__nv_bfloat16(*)[136])(st + 20480);
        __nv_bfloat16 (*Bl)[136] = (__nv_bfloat16(*)[136])(st + 29184);
#pragma unroll
        for (int ks = 0; ks < 32; ks += 16) {
            uint32_t ahh[2][4], all[2][4];
#pragma unroll
            for (int i = 0; i < 2; i++) {
                ldm_x4(ahh[i], &Ah[wm * 32 + i * 16 + a_row][ks + a_col]);
                ldm_x4(all[i], &Al[wm * 32 + i * 16 + a_row][ks + a_col]);
            }
            uint32_t bhh[8][2], bll[8][2];
#pragma unroll
            for (int jj = 0; jj < 4; jj++) {
                uint32_t rh[4], rl[4];
                ldm_x4_t(rh, &Bh[ks + b_k][wn * 64 + jj * 16 + b_n8]);
                ldm_x4_t(rl, &Bl[ks + b_k][wn * 64 + jj * 16 + b_n8]);
                bhh[2 * jj][0] = rh[0]; bhh[2 * jj][1] = rh[1];
                bhh[2 * jj + 1][0] = rh[2]; bhh[2 * jj + 1][1] = rh[3];
                bll[2 * jj][0] = rl[0]; bll[2 * jj][1] = rl[1];
                bll[2 * jj + 1][0] = rl[2]; bll[2 * jj + 1][1] = rl[3];
            }
#pragma unroll
            for (int i = 0; i < 2; i++)
#pragma unroll
                for (int j = 0; j < 8; j++) {
                    mma_bf16(acc[i][j], ahh[i], bll[j]);
                    mma_bf16(acc[i][j], all[i], bhh[j]);
                    mma_bf16(acc[i][j], ahh[i], bhh[j]);
                }
        }
        __syncthreads();
    }

#pragma unroll
    for (int i = 0; i < 2; i++)
#pragma unroll
        for (int half = 0; half < 2; half++) {
            int gr = row0 + wm * 32 + i * 16 + half * 8 + g;
            if (gr >= NN) continue;
            float* dst = &g_uv[gr * 256 + halfsel * 128 + wn * 64 + 2 * tg];
#pragma unroll
            for (int j = 0; j < 8; j++) {
                float2 v = half ? make_float2(acc[i][j].z, acc[i][j].w)
                                : make_float2(acc[i][j].x, acc[i][j].y);
                *(float2*)(dst + j * 8) = v;
            }
        }
}

// ---------------- pair kernel: out = GELU(u[i]+v[j]+mb1) @ mw2 + mb2 ----------------
__global__ void k_pair(const int* __restrict__ edges, const float* __restrict__ mb1,
                       const float* __restrict__ mw2, const float* __restrict__ mb2,
                       float* __restrict__ out) {
    __shared__ float sw2[HID * NCLS];
    __shared__ float sb1[HID];
    __shared__ float sb2[NCLS];
    const int t = threadIdx.x;
    for (int l = t; l < HID * NCLS; l += 256) sw2[l] = mw2[l];
    if (t < HID) sb1[t] = mb1[t];
    if (t < NCLS) sb2[t] = mb2[t];
    __syncthreads();
    int p = blockIdx.x * 8 + (t >> 5);
    int lane = t & 31;
    int2 pr = ((const int2*)edges)[p];
    float4 uu = *(const float4*)&g_uv[pr.x * 256 + lane * 4];
    float4 vv = *(const float4*)&g_uv[pr.y * 256 + 128 + lane * 4];
    float4 bb = *(const float4*)&sb1[lane * 4];
    float4 z;
    z.x = uu.x + vv.x + bb.x;
    z.y = uu.y + vv.y + bb.y;
    z.z = uu.z + vv.z + bb.z;
    z.w = uu.w + vv.w + bb.w;
    z.x = 0.5f * z.x * (1.f + erff(z.x * 0.70710678118654752f));
    z.y = 0.5f * z.y * (1.f + erff(z.y * 0.70710678118654752f));
    z.z = 0.5f * z.z * (1.f + erff(z.z * 0.70710678118654752f));
    z.w = 0.5f * z.w * (1.f + erff(z.w * 0.70710678118654752f));
    const float* w = sw2 + lane * 4 * NCLS;
    float acc[NCLS];
#pragma unroll
    for (int c = 0; c < NCLS; c++)
        acc[c] = z.x * w[c] + z.y * w[NCLS + c] + z.z * w[2 * NCLS + c] + z.w * w[3 * NCLS + c];
#pragma unroll
    for (int o = 16; o >= 1; o >>= 1)
#pragma unroll
        for (int c = 0; c < NCLS; c++) acc[c] += __shfl_xor_sync(0xffffffffu, acc[c], o);
    if (lane < NCLS) out[p * NCLS + lane] = acc[lane] + sb2[lane];
}

// ---------------- launch (multi-stream fork/join, graph-capturable) ----------------
extern "C" void kernel_launch(void* const* d_in, const int* in_sizes, int n_in,
                              void* d_out, int out_size) {
    const float* x     = (const float*)d_in[0];
    const int*   ei    = (const int*)d_in[1];
    const int*   et    = (const int*)d_in[2];
    const int*   edges = (const int*)d_in[3];
    const float* w1 = (const float*)d_in[4];
    const float* q1 = (const float*)d_in[5];
    const float* k1 = (const float*)d_in[6];
    const float* b1 = (const float*)d_in[7];
    const float* w2 = (const float*)d_in[8];
    const float* q2 = (const float*)d_in[9];
    const float* k2 = (const float*)d_in[10];
    const float* b2 = (const float*)d_in[11];
    const float* ln1g = (const float*)d_in[12];
    const float* ln1b = (const float*)d_in[13];
    const float* ln2g = (const float*)d_in[14];
    const float* ln2b = (const float*)d_in[15];
    const float* mw1 = (const float*)d_in[16];
    const float* mb1 = (const float*)d_in[17];
    const float* mw2 = (const float*)d_in[18];
    const float* mb2 = (const float*)d_in[19];
    float* out = (float*)d_out;

    static cudaStream_t s1 = nullptr, s2 = nullptr;
    static cudaEvent_t evStart, evPrep, evW0, evFill, evA0, evH1, evA1;
    if (!s1) {
        cudaStreamCreateWithFlags(&s1, cudaStreamNonBlocking);
        cudaStreamCreateWithFlags(&s2, cudaStreamNonBlocking);
        cudaEventCreateWithFlags(&evStart, cudaEventDisableTiming);
        cudaEventCreateWithFlags(&evPrep,  cudaEventDisableTiming);
        cudaEventCreateWithFlags(&evW0,    cudaEventDisableTiming);
        cudaEventCreateWithFlags(&evFill,  cudaEventDisableTiming);
        cudaEventCreateWithFlags(&evA0,    cudaEventDisableTiming);
        cudaEventCreateWithFlags(&evH1,    cudaEventDisableTiming);
        cudaEventCreateWithFlags(&evA1,    cudaEventDisableTiming);
        cudaFuncSetAttribute(k_gemm16, cudaFuncAttributeMaxDynamicSharedMemorySize, 2 * G_STAGE);
        cudaFuncSetAttribute(k_uv,     cudaFuncAttributeMaxDynamicSharedMemorySize, 2 * STAGE_BYTES);
    }

    const int prepTot = NN * HID / 4 + 2 * (RR * HID * HID / 4) + 2 * HID * HID / 4;
    const dim3 gXW((NN + 127) / 128, RR);
    const dim3 gUV((NN + 127) / 128, 2);

    cudaEventRecord(evStart, 0);
    cudaStreamWaitEvent(s1, evStart, 0);

    // side stream 1: wqk planes + CSR build
    k_wqk<<<(64 * HID + 255) / 256, 256, 0, s1>>>(w1, q1, k1, 0);
    cudaEventRecord(evW0, s1);
    k_wqk<<<(64 * HID + 255) / 256, 256, 0, s1>>>(w2, q2, k2, 1);
    k_zero<<<(NN + 255) / 256, 256, 0, s1>>>();
    k_hist<<<(EE + 255) / 256, 256, 0, s1>>>(ei);
    k_scan<<<1, 1024, 0, s1>>>();
    k_fill<<<(EE + 255) / 256, 256, 0, s1>>>(ei, et);
    cudaEventRecord(evFill, s1);

    // main: prep -> gemm(0)
    k_prep<<<(prepTot + 255) / 256, 256>>>(x, w1, w2, mw1);
    cudaEventRecord(evPrep, 0);

    cudaStreamWaitEvent(s2, evStart, 0);
    cudaStreamWaitEvent(s2, evPrep, 0);
    cudaStreamWaitEvent(s2, evW0, 0);
    k_aqk<<<(NN + 127) / 128, 256, 0, s2>>>(0);
    cudaEventRecord(evA0, s2);

    k_gemm16<<<gXW, 256, 2 * G_STAGE>>>(0);
    cudaStreamWaitEvent(0, evA0, 0);
    cudaStreamWaitEvent(0, evFill, 0);
    k_agg_ln<<<(NN + 7) / 8, 256>>>(b1, ln1g, ln1b, 1);
    cudaEventRecord(evH1, 0);

    cudaStreamWaitEvent(s2, evH1, 0);
    k_aqk<<<(NN + 127) / 128, 256, 0, s2>>>(1);
    cudaEventRecord(evA1, s2);

    k_gemm16<<<gXW, 256, 2 * G_STAGE>>>(1);
    cudaStreamWaitEvent(0, evA1, 0);
    k_agg_ln<<<(NN + 7) / 8, 256>>>(b2, ln2g, ln2b, 2);

    k_uv<<<gUV, 256, 2 * STAGE_BYTES>>>();
    k_pair<<<EE2 / 8, 256>>>(edges, mb1, mw2, mb2, out);
}

// round 16
// speedup vs baseline: 1.2439x; 1.2439x over previous
#include <cuda_runtime.h>
#include <cuda_bf16.h>
#include <cuda_fp16.h>
#include <math.h>
#include <stdint.h>

#define NN   50000
#define HID  128
#define RR   8
#define EE   640000
#define EE2  200000
#define NCLS 8

// ---------------- scratch (device globals; allocation-free) ----------------
__device__ __half g_xw[NN * RR * HID];
__device__ float g_aq[NN * RR * 4];
__device__ float g_ak[NN * RR * 4];
__device__ __half g_x16[NN * HID], g_h116[NN * HID];
__device__ __nv_bfloat16 g_xhi[NN * HID],  g_xlo[NN * HID];
__device__ __nv_bfloat16 g_h1hi[NN * HID], g_h1lo[NN * HID];
__device__ __nv_bfloat16 g_hshi[NN * HID], g_hslo[NN * HID];
__device__ __half g_w16[2 * RR * HID * HID];                     // [layer][r][k][n]
__device__ __nv_bfloat16 g_m1hi[2 * HID * HID], g_m1lo[2 * HID * HID]; // [k=256][n=128]
__device__ __nv_bfloat16 g_qkhi[2][64 * HID], g_qklo[2][64 * HID];
__device__ int g_deg[NN], g_rowptr[NN + 1], g_cursor[NN], g_csr[EE];

// ---------------- helpers ----------------
__device__ __forceinline__ void bsplit(float v, __nv_bfloat16& hi, __nv_bfloat16& lo) {
    hi = __float2bfloat16(v);
    lo = __float2bfloat16(v - __bfloat162float(hi));
}
__device__ __forceinline__ void mma_bf16(float4& d, const uint32_t* a, const uint32_t* b) {
    asm volatile(
        "mma.sync.aligned.m16n8k16.row.col.f32.bf16.bf16.f32 "
        "{%0,%1,%2,%3}, {%4,%5,%6,%7}, {%8,%9}, {%0,%1,%2,%3};"
        : "+f"(d.x), "+f"(d.y), "+f"(d.z), "+f"(d.w)
        : "r"(a[0]), "r"(a[1]), "r"(a[2]), "r"(a[3]), "r"(b[0]), "r"(b[1]));
}
__device__ __forceinline__ void mma_f16(float4& d, const uint32_t* a, const uint32_t* b) {
    asm volatile(
        "mma.sync.aligned.m16n8k16.row.col.f32.f16.f16.f32 "
        "{%0,%1,%2,%3}, {%4,%5,%6,%7}, {%8,%9}, {%0,%1,%2,%3};"
        : "+f"(d.x), "+f"(d.y), "+f"(d.z), "+f"(d.w)
        : "r"(a[0]), "r"(a[1]), "r"(a[2]), "r"(a[3]), "r"(b[0]), "r"(b[1]));
}
__device__ __forceinline__ void ldm_x4(uint32_t* r, const void* p) {
    uint32_t a = (uint32_t)__cvta_generic_to_shared(p);
    asm volatile("ldmatrix.sync.aligned.m8n8.x4.shared.b16 {%0,%1,%2,%3}, [%4];"
                 : "=r"(r[0]), "=r"(r[1]), "=r"(r[2]), "=r"(r[3]) : "r"(a));
}
__device__ __forceinline__ void ldm_x4_t(uint32_t* r, const void* p) {
    uint32_t a = (uint32_t)__cvta_generic_to_shared(p);
    asm volatile("ldmatrix.sync.aligned.m8n8.x4.trans.shared.b16 {%0,%1,%2,%3}, [%4];"
                 : "=r"(r[0]), "=r"(r[1]), "=r"(r[2]), "=r"(r[3]) : "r"(a));
}
__device__ __forceinline__ void cpa(uint32_t d, const void* s) {
    asm volatile("cp.async.cg.shared.global [%0], [%1], 16;" :: "r"(d), "l"(s));
}
__device__ __forceinline__ void cp_commit() { asm volatile("cp.async.commit_group;"); }
__device__ __forceinline__ void cp_wait0() { asm volatile("cp.async.wait_group 0;"); }
__device__ __forceinline__ void cp_wait1() { asm volatile("cp.async.wait_group 1;"); }
__device__ __forceinline__ void cp_wait2() { asm volatile("cp.async.wait_group 2;"); }

#define STAGE_BYTES 37888   // decode stage: Ah 0, Al 10240, Bh 20480, Bl 29184
#define G_STAGE 18944       // fp16 gemm stage: A 0 (10240), B 10240 (8704)

// ---------------- CSR build ----------------
__global__ void k_zero() {
    int i = blockIdx.x * blockDim.x + threadIdx.x;
    if (i < NN) g_deg[i] = 0;
}
__global__ void k_hist(const int* __restrict__ ei) {
    int e = blockIdx.x * blockDim.x + threadIdx.x;
    if (e < EE) atomicAdd(&g_deg[ei[EE + e]], 1);
}
__global__ void k_scan() {
    __shared__ int sp[1024];
    const int t = threadIdx.x;
    const int chunk = (NN + 1023) / 1024;
    int start = t * chunk, end = min(start + chunk, NN);
    int s = 0;
    for (int i = start; i < end; i++) s += g_deg[i];
    sp[t] = s;
    __syncthreads();
    for (int off = 1; off < 1024; off <<= 1) {
        int v = (t >= off) ? sp[t - off] : 0;
        __syncthreads();
        sp[t] += v;
        __syncthreads();
    }
    int run = (t == 0) ? 0 : sp[t - 1];
    for (int i = start; i < end; i++) {
        g_rowptr[i] = run;
        g_cursor[i] = run;
        run += g_deg[i];
    }
    if (t == 1023) g_rowptr[NN] = run;
}
__global__ void k_fill(const int* __restrict__ ei, const int* __restrict__ et) {
    int e = blockIdx.x * blockDim.x + threadIdx.x;
    if (e >= EE) return;
    int dst = ei[EE + e];
    int pos = atomicAdd(&g_cursor[dst], 1);
    g_csr[pos] = ei[e] * 8 + et[e];
}

// ---------------- fused prep: x -> {fp16, bf16 hi/lo}; W -> fp16; mw1 -> bf16 hi/lo ----------------
__global__ void k_prep(const float* __restrict__ x, const float* __restrict__ w1,
                       const float* __restrict__ w2, const float* __restrict__ mw1) {
    const int R0 = NN * HID / 4;
    const int R1 = RR * HID * HID / 4;
    const int R3 = 2 * HID * HID / 4;
    int id = blockIdx.x * blockDim.x + threadIdx.x;
    if (id < R0) {
        float4 v = ((const float4*)x)[id];
        union { __nv_bfloat16 b[4]; uint2 u; } ph, pl;
        bsplit(v.x, ph.b[0], pl.b[0]); bsplit(v.y, ph.b[1], pl.b[1]);
        bsplit(v.z, ph.b[2], pl.b[2]); bsplit(v.w, ph.b[3], pl.b[3]);
        *(uint2*)&g_xhi[id * 4] = ph.u;
        *(uint2*)&g_xlo[id * 4] = pl.u;
        __half2 h0 = __floats2half2_rn(v.x, v.y);
        __half2 h1 = __floats2half2_rn(v.z, v.w);
        uint2 u16;
        u16.x = *(uint32_t*)&h0; u16.y = *(uint32_t*)&h1;
        *(uint2*)&g_x16[id * 4] = u16;
    } else if (id < R0 + 2 * R1) {
        int layer = (id - R0) >= R1;
        int off = id - R0 - layer * R1;
        const float* src = layer ? w2 : w1;
        float4 v = ((const float4*)src)[off];
        __half2 h0 = __floats2half2_rn(v.x, v.y);
        __half2 h1 = __floats2half2_rn(v.z, v.w);
        uint2 u16;
        u16.x = *(uint32_t*)&h0; u16.y = *(uint32_t*)&h1;
        *(uint2*)&g_w16[layer * RR * HID * HID + off * 4] = u16;
    } else if (id < R0 + 2 * R1 + R3) {
        int off = id - R0 - 2 * R1;
        float4 v = ((const float4*)mw1)[off];
        union { __nv_bfloat16 b[4]; uint2 u; } ph, pl;
        bsplit(v.x, ph.b[0], pl.b[0]); bsplit(v.y, ph.b[1], pl.b[1]);
        bsplit(v.z, ph.b[2], pl.b[2]); bsplit(v.w, ph.b[3], pl.b[3]);
        *(uint2*)&g_m1hi[off * 4] = ph.u;
        *(uint2*)&g_m1lo[off * 4] = pl.u;
    }
}

// ---------------- Wqk planes ----------------
__global__ void k_wqk(const float* __restrict__ W, const float* __restrict__ q,
                      const float* __restrict__ kk, int layer) {
    int id = blockIdx.x * blockDim.x + threadIdx.x;
    if (id >= 64 * HID) return;
    int i = id & 127, n = id >> 7;
    int h = n & 3, r = (n >> 2) & 7;
    const float* vq = (n < 32) ? q : kk;
    const float* wrow = W + r * HID * HID + i * HID;
    float s = 0.f;
#pragma unroll 4
    for (int o = 0; o < HID; o++) s += wrow[o] * vq[o * 4 + h];
    bsplit(s, g_qkhi[layer][n * HID + i], g_qklo[layer][n * HID + i]);
}

// ---------------- fp16 single-plane GEMM (3-stage cp.async): xw = A @ W[layer][r] ----------------
__global__ void __launch_bounds__(256, 2)
k_gemm16(int layer) {
    extern __shared__ char smem[];
    const int t = threadIdx.x, lane = t & 31, wid = t >> 5;
    const int wm = wid & 3, wn = wid >> 2, g = lane >> 2, tg = lane & 3;
    const int r = blockIdx.y, row0 = blockIdx.x * 128;
    const __half* A = layer ? g_h116 : g_x16;
    const __half* B = g_w16 + (layer * RR + r) * HID * HID;

    const int lr = t >> 1, lc = (t & 1) * 16;
    const int garow = row0 + lr;
    const __half* asrc = (garow < NN ? A + garow * 128 : A) + lc;
    const int bk = t >> 3, bn = (t & 7) * 16;

    uint32_t sbase = (uint32_t)__cvta_generic_to_shared(smem);
    uint32_t a_d[3], b_d[3];
#pragma unroll
    for (int s = 0; s < 3; s++) {
        uint32_t sb = sbase + s * G_STAGE;
        a_d[s] = sb + (lr * 40 + lc) * 2;
        b_d[s] = sb + 10240 + (bk * 136 + bn) * 2;
    }
    auto issue = [&](int k0, int s) {
        cpa(a_d[s], asrc + k0);  cpa(a_d[s] + 16, asrc + k0 + 8);
        const __half* bp = B + (k0 + bk) * 128 + bn;
        cpa(b_d[s], bp);         cpa(b_d[s] + 16, bp + 8);
        cp_commit();
    };

    float4 acc[2][8];
#pragma unroll
    for (int i = 0; i < 2; i++)
#pragma unroll
        for (int j = 0; j < 8; j++) acc[i][j] = make_float4(0.f, 0.f, 0.f, 0.f);

    const int a_row = lane & 15, a_col = ((lane >> 4) & 1) * 8;
    const int b_k = (lane & 7) + ((lane & 8) ? 8 : 0);
    const int b_n8 = (lane & 16) ? 8 : 0;

    issue(0, 0);
    issue(32, 1);
    for (int it = 0; it < 4; it++) {
        if (it < 2) { issue((it + 2) * 32, (it + 2) % 3); cp_wait2(); }
        else if (it == 2) cp_wait1();
        else cp_wait0();
        __syncthreads();
        char* st = smem + (it % 3) * G_STAGE;
        __half (*Ah)[40]  = (__half(*)[40])(st);
        __half (*Bh)[136] = (__half(*)[136])(st + 10240);
#pragma unroll
        for (int ks = 0; ks < 32; ks += 16) {
            uint32_t af[2][4];
#pragma unroll
            for (int i = 0; i < 2; i++)
                ldm_x4(af[i], &Ah[wm * 32 + i * 16 + a_row][ks + a_col]);
            uint32_t bf[8][2];
#pragma unroll
            for (int jj = 0; jj < 4; jj++) {
                uint32_t rh[4];
                ldm_x4_t(rh, &Bh[ks + b_k][wn * 64 + jj * 16 + b_n8]);
                bf[2 * jj][0] = rh[0]; bf[2 * jj][1] = rh[1];
                bf[2 * jj + 1][0] = rh[2]; bf[2 * jj + 1][1] = rh[3];
            }
#pragma unroll
            for (int i = 0; i < 2; i++)
#pragma unroll
                for (int j = 0; j < 8; j++)
                    mma_f16(acc[i][j], af[i], bf[j]);
        }
        __syncthreads();
    }

    // store xw fp16
#pragma unroll
    for (int i = 0; i < 2; i++)
#pragma unroll
        for (int half = 0; half < 2; half++) {
            int gr = row0 + wm * 32 + i * 16 + half * 8 + g;
            if (gr < NN) {
                __half* dst = &g_xw[(gr * 8 + r) * 128 + wn * 64 + 2 * tg];
#pragma unroll
                for (int j = 0; j < 8; j++) {
                    float2 v = half ? make_float2(acc[i][j].z, acc[i][j].w)
                                    : make_float2(acc[i][j].x, acc[i][j].y);
                    *(__half2*)(dst + j * 8) = __floats2half2_rn(v.x, v.y);
                }
            }
        }
}

// ---------------- aq/ak GEMM (bf16x3) ----------------
__global__ void __launch_bounds__(256)
k_aqk(int layer) {
    __shared__ __nv_bfloat16 Ah[128][40], Al[128][40], Bh[64][40], Bl[64][40];
    const int t = threadIdx.x, lane = t & 31, wid = t >> 5;
    const int wm = wid & 3, wn = wid >> 2, g = lane >> 2, tg = lane & 3;
    const int row0 = blockIdx.x * 128;
    const __nv_bfloat16* Ahi = layer ? g_h1hi : g_xhi;
    const __nv_bfloat16* Alo = layer ? g_h1lo : g_xlo;
    const __nv_bfloat16* Bhi = g_qkhi[layer];
    const __nv_bfloat16* Blo = g_qklo[layer];

    const int lr = t >> 1, lc = (t & 1) * 16;
    const int garow = row0 + lr;
    const __nv_bfloat16* ahp = (garow < NN ? Ahi + garow * 128 : Ahi) + lc;
    const __nv_bfloat16* alp = (garow < NN ? Alo + garow * 128 : Alo) + lc;
    const int br = t >> 2, bc = (t & 3) * 8;

    float4 acc[2][4];
#pragma unroll
    for (int i = 0; i < 2; i++)
#pragma unroll
        for (int j = 0; j < 4; j++) acc[i][j] = make_float4(0.f, 0.f, 0.f, 0.f);

    const int a_row = lane & 15, a_col = ((lane >> 4) & 1) * 8;
    const int b_row = (lane & 7) + ((lane & 16) ? 8 : 0);
    const int b_col = (lane & 8) ? 8 : 0;

    for (int k0 = 0; k0 < 128; k0 += 32) {
        uint4 a0 = *(const uint4*)(ahp + k0);
        uint4 a1 = *(const uint4*)(ahp + k0 + 8);
        uint4 a2 = *(const uint4*)(alp + k0);
        uint4 a3 = *(const uint4*)(alp + k0 + 8);
        uint4 b0 = *(const uint4*)&Bhi[br * 128 + k0 + bc];
        uint4 b1 = *(const uint4*)&Blo[br * 128 + k0 + bc];
        __syncthreads();
        *(uint4*)&Ah[lr][lc] = a0; *(uint4*)&Ah[lr][lc + 8] = a1;
        *(uint4*)&Al[lr][lc] = a2; *(uint4*)&Al[lr][lc + 8] = a3;
        *(uint4*)&Bh[br][bc] = b0;
        *(uint4*)&Bl[br][bc] = b1;
        __syncthreads();
#pragma unroll
        for (int ks = 0; ks < 32; ks += 16) {
            uint32_t ahh[2][4], all[2][4];
#pragma unroll
            for (int i = 0; i < 2; i++) {
                ldm_x4(ahh[i], &Ah[wm * 32 + i * 16 + a_row][ks + a_col]);
                ldm_x4(all[i], &Al[wm * 32 + i * 16 + a_row][ks + a_col]);
            }
            uint32_t bhh[4][2], bll[4][2];
#pragma unroll
            for (int jj = 0; jj < 2; jj++) {
                uint32_t rh[4], rl[4];
                ldm_x4(rh, &Bh[wn * 32 + jj * 16 + b_row][ks + b_col]);
                ldm_x4(rl, &Bl[wn * 32 + jj * 16 + b_row][ks + b_col]);
                bhh[2 * jj][0] = rh[0]; bhh[2 * jj][1] = rh[1];
                bhh[2 * jj + 1][0] = rh[2]; bhh[2 * jj + 1][1] = rh[3];
                bll[2 * jj][0] = rl[0]; bll[2 * jj][1] = rl[1];
                bll[2 * jj + 1][0] = rl[2]; bll[2 * jj + 1][1] = rl[3];
            }
#pragma unroll
            for (int i = 0; i < 2; i++)
#pragma unroll
                for (int j = 0; j < 4; j++) {
                    mma_bf16(acc[i][j], ahh[i], bll[j]);
                    mma_bf16(acc[i][j], all[i], bhh[j]);
                    mma_bf16(acc[i][j], ahh[i], bhh[j]);
                }
        }
    }

#pragma unroll
    for (int i = 0; i < 2; i++)
#pragma unroll
        for (int half = 0; half < 2; half++) {
            int gr = row0 + wm * 32 + i * 16 + half * 8 + g;
            if (gr >= NN) continue;
#pragma unroll
            for (int j = 0; j < 4; j++) {
                int col = wn * 32 + j * 8 + 2 * tg;
                float2 v = half ? make_float2(acc[i][j].z, acc[i][j].w)
                                : make_float2(acc[i][j].x, acc[i][j].y);
                if (col < 32) *(float2*)&g_aq[gr * 32 + col] = v;
                else          *(float2*)&g_ak[gr * 32 + col - 32] = v;
            }
        }
}

// ---------------- fused per-node softmax + aggregate + bias + relu + LN ----------------
__global__ void k_agg_ln(const float* __restrict__ bias, const float* __restrict__ gam,
                         const float* __restrict__ bet, int layer) {
    int nid = blockIdx.x * 8 + (threadIdx.x >> 5);
    if (nid >= NN) return;
    int lane = threadIdx.x & 31;
    int h = lane >> 3;
    int e8 = lane & 7;
    int j0 = g_rowptr[nid], j1 = g_rowptr[nid + 1];
    float aqr = g_aq[nid * 32 + lane];
    float4 num = make_float4(0.f, 0.f, 0.f, 0.f);
    float den = 0.f;

    int base = j0;
    for (; base + 8 <= j1; base += 8) {
        int p = g_csr[base + e8];
        int rr = p & 7;
        float aqv = __shfl_sync(0xffffffffu, aqr, rr * 4 + h);
        float a = aqv + g_ak[p * 4 + h];
        a = a > 0.f ? a : 0.2f * a;
        float ex = __expf(a);
        den += ex;
        uint2 rbuf[8];
#pragma unroll
        for (int e = 0; e < 8; e++) {
            int pe = __shfl_sync(0xffffffffu, p, e);
            rbuf[e] = *(const uint2*)&g_xw[pe * 128 + lane * 4];
        }
#pragma unroll
        for (int e = 0; e < 8; e++) {
            float exe = __shfl_sync(0xffffffffu, ex, (lane & 24) + e);
            float2 f0 = __half22float2(*(__half2*)&rbuf[e].x);
            float2 f1 = __half22float2(*(__half2*)&rbuf[e].y);
            num.x += exe * f0.x; num.y += exe * f0.y;
            num.z += exe * f1.x; num.w += exe * f1.y;
        }
    }
    if (base < j1) {
        int idx = base + e8;
        bool ok = idx < j1;
        int p = ok ? g_csr[idx] : 0;
        int rr = p & 7;
        float aqv = __shfl_sync(0xffffffffu, aqr, rr * 4 + h);
        float ex = 0.f;
        if (ok) {
            float a = aqv + g_ak[p * 4 + h];
            a = a > 0.f ? a : 0.2f * a;
            ex = __expf(a);
        }
        den += ex;
        int cnt = j1 - base;
        for (int e = 0; e < cnt; e++) {
            float exe = __shfl_sync(0xffffffffu, ex, (lane & 24) + e);
            int pe = __shfl_sync(0xffffffffu, p, e);
            uint2 raw = *(const uint2*)&g_xw[pe * 128 + lane * 4];
            float2 f0 = __half22float2(*(__half2*)&raw.x);
            float2 f1 = __half22float2(*(__half2*)&raw.y);
            num.x += exe * f0.x; num.y += exe * f0.y;
            num.z += exe * f1.x; num.w += exe * f1.y;
        }
    }

    den += __shfl_xor_sync(0xffffffffu, den, 1);
    den += __shfl_xor_sync(0xffffffffu, den, 2);
    den += __shfl_xor_sync(0xffffffffu, den, 4);
    float inv = 1.f / (den + 1e-16f);
    float4 bb = *(const float4*)&bias[lane * 4];
    float4 v;
    v.x = fmaxf(num.x * inv + bb.x, 0.f);
    v.y = fmaxf(num.y * inv + bb.y, 0.f);
    v.z = fmaxf(num.z * inv + bb.z, 0.f);
    v.w = fmaxf(num.w * inv + bb.w, 0.f);
    float s = v.x + v.y + v.z + v.w;
#pragma unroll
    for (int o = 16; o >= 1; o >>= 1) s += __shfl_xor_sync(0xffffffffu, s, o);
    float mean = s * (1.f / 128.f);
    float dx = v.x - mean, dy = v.y - mean, dz = v.z - mean, dw = v.w - mean;
    float ss = dx * dx + dy * dy + dz * dz + dw * dw;
#pragma unroll
    for (int o = 16; o >= 1; o >>= 1) ss += __shfl_xor_sync(0xffffffffu, ss, o);
    float rs = rsqrtf(ss * (1.f / 128.f) + 1e-5f);
    float4 g4 = *(const float4*)&gam[lane * 4];
    float4 b4 = *(const float4*)&bet[lane * 4];
    float4 y;
    y.x = dx * rs * g4.x + b4.x;
    y.y = dy * rs * g4.y + b4.y;
    y.z = dz * rs * g4.z + b4.z;
    y.w = dw * rs * g4.w + b4.w;
    union { __nv_bfloat16 b[4]; uint2 u; } ph, pl;
    if (layer == 1) {
        bsplit(y.x, ph.b[0], pl.b[0]); bsplit(y.y, ph.b[1], pl.b[1]);
        bsplit(y.z, ph.b[2], pl.b[2]); bsplit(y.w, ph.b[3], pl.b[3]);
        *(uint2*)&g_h1hi[nid * HID + lane * 4] = ph.u;
        *(uint2*)&g_h1lo[nid * HID + lane * 4] = pl.u;
        __half2 h0 = __floats2half2_rn(y.x, y.y);
        __half2 h1 = __floats2half2_rn(y.z, y.w);
        uint2 u16;
        u16.x = *(uint32_t*)&h0; u16.y = *(uint32_t*)&h1;
        *(uint2*)&g_h116[nid * HID + lane * 4] = u16;
    } else {
        uint2 rh = *(const uint2*)&g_h1hi[nid * HID + lane * 4];
        uint2 rl = *(const uint2*)&g_h1lo[nid * HID + lane * 4];
        const __nv_bfloat16* hb = (const __nv_bfloat16*)&rh;
        const __nv_bfloat16* lb = (const __nv_bfloat16*)&rl;
        y.x += __bfloat162float(hb[0]) + __bfloat162float(lb[0]);
        y.y += __bfloat162float(hb[1]) + __bfloat162float(lb[1]);
        y.z += __bfloat162float(hb[2]) + __bfloat162float(lb[2]);
        y.w += __bfloat162float(hb[3]) + __bfloat162float(lb[3]);
        bsplit(y.x, ph.b[0], pl.b[0]); bsplit(y.y, ph.b[1], pl.b[1]);
        bsplit(y.z, ph.b[2], pl.b[2]); bsplit(y.w, ph.b[3], pl.b[3]);
        *(uint2*)&g_hshi[nid * HID + lane * 4] = ph.u;
        *(uint2*)&g_hslo[nid * HID + lane * 4] = pl.u;
    }
}

// ---------------- decode (bf16x3 fused; round-13 validated version) ----------------
__global__ void __launch_bounds__(256, 2)
k_decode1(const int* __restrict__ edges, const float* __restrict__ mb1,
          const float* __restrict__ mw2, const float* __restrict__ mb2,
          float* __restrict__ out) {
    extern __shared__ char smem[];
    __shared__ int sidx[128][2];
    __shared__ float sb[128];
    __shared__ float sw2[128][NCLS];
    __shared__ float s_out[128][NCLS];

    const int t = threadIdx.x, lane = t & 31, wid = t >> 5;
    const int wm = wid & 3, wn = wid >> 2, g = lane >> 2, tg = lane & 3;
    const int row0 = blockIdx.x * 128;

    if (t < 128) {
        int p = row0 + t;
        int2 pr = (p < EE2) ? ((const int2*)edges)[p] : make_int2(0, 0);
        sidx[t][0] = pr.x;
        sidx[t][1] = pr.y;
        sb[t] = mb1[t];
        *(float4*)&sw2[t][0] = *(const float4*)&mw2[t * NCLS];
        *(float4*)&sw2[t][4] = *(const float4*)&mw2[t * NCLS + 4];
        *(float4*)&s_out[t][0] = make_float4(0.f, 0.f, 0.f, 0.f);
        *(float4*)&s_out[t][4] = make_float4(0.f, 0.f, 0.f, 0.f);
    }
    __syncthreads();

    const int lr = t >> 1, lc = (t & 1) * 16;
    const int node0 = sidx[lr][0];
    const int node1 = sidx[lr][1];
    const int bk = t >> 3, bn = (t & 7) * 16;

    uint32_t sbase = (uint32_t)__cvta_generic_to_shared(smem);
    uint32_t ah_d[2], al_d[2], bh_d[2], bl_d[2];
#pragma unroll
    for (int s = 0; s < 2; s++) {
        uint32_t sb2 = sbase + s * STAGE_BYTES;
        ah_d[s] = sb2 + (lr * 40 + lc) * 2;
        al_d[s] = sb2 + 10240 + (lr * 40 + lc) * 2;
        bh_d[s] = sb2 + 20480 + (bk * 136 + bn) * 2;
        bl_d[s] = sb2 + 29184 + (bk * 136 + bn) * 2;
    }
    auto issue = [&](int c, int s) {
        int node = (c < 4) ? node0 : node1;
        int colbase = (c & 3) * 32 + lc;
        const __nv_bfloat16* ah = &g_hshi[node * 128 + colbase];
        const __nv_bfloat16* al = &g_hslo[node * 128 + colbase];
        cpa(ah_d[s], ah);  cpa(ah_d[s] + 16, ah + 8);
        cpa(al_d[s], al);  cpa(al_d[s] + 16, al + 8);
        const __nv_bfloat16* bh = &g_m1hi[(c * 32 + bk) * 128 + bn];
        const __nv_bfloat16* bl = &g_m1lo[(c * 32 + bk) * 128 + bn];
        cpa(bh_d[s], bh);  cpa(bh_d[s] + 16, bh + 8);
        cpa(bl_d[s], bl);  cpa(bl_d[s] + 16, bl + 8);
        cp_commit();
    };

    float4 acc[2][8];
#pragma unroll
    for (int i = 0; i < 2; i++)
#pragma unroll
        for (int j = 0; j < 8; j++) acc[i][j] = make_float4(0.f, 0.f, 0.f, 0.f);

    const int a_row = lane & 15, a_col = ((lane >> 4) & 1) * 8;
    const int b_k = (lane & 7) + ((lane & 8) ? 8 : 0);
    const int b_n8 = (lane & 16) ? 8 : 0;

    issue(0, 0);
    for (int it = 0; it < 8; it++) {
        if (it < 7) { issue(it + 1, (it + 1) & 1); cp_wait1(); }
        else cp_wait0();
        __syncthreads();
        char* st = smem + (it & 1) * STAGE_BYTES;
        __nv_bfloat16 (*Ah)[40]  = (__nv_bfloat16(*)[40])(st);
        __nv_bfloat16 (*Al)[40]  = (__nv_bfloat16(*)[40])(st + 10240);
        __nv_bfloat16 (*Bh)[136] = (__nv_bfloat16(*)[136])(st + 20480);
        __nv_bfloat16 (*Bl)[136] = (__nv_bfloat16(*)[136])(st + 29184);
#pragma unroll
        for (int ks = 0; ks < 32; ks += 16) {
            uint32_t ahh[2][4], all[2][4];
#pragma unroll
            for (int i = 0; i < 2; i++) {
                ldm_x4(ahh[i], &Ah[wm * 32 + i * 16 + a_row][ks + a_col]);
                ldm_x4(all[i], &Al[wm * 32 + i * 16 + a_row][ks + a_col]);
            }
            uint32_t bhh[8][2], bll[8][2];
#pragma unroll
            for (int jj = 0; jj < 4; jj++) {
                uint32_t rh[4], rl[4];
                ldm_x4_t(rh, &Bh[ks + b_k][wn * 64 + jj * 16 + b_n8]);
                ldm_x4_t(rl, &Bl[ks + b_k][wn * 64 + jj * 16 + b_n8]);
                bhh[2 * jj][0] = rh[0]; bhh[2 * jj][1] = rh[1];
                bhh[2 * jj + 1][0] = rh[2]; bhh[2 * jj + 1][1] = rh[3];
                bll[2 * jj][0] = rl[0]; bll[2 * jj][1] = rl[1];
                bll[2 * jj + 1][0] = rl[2]; bll[2 * jj + 1][1] = rl[3];
            }
#pragma unroll
            for (int i = 0; i < 2; i++)
#pragma unroll
                for (int j = 0; j < 8; j++) {
                    mma_bf16(acc[i][j], ahh[i], bll[j]);
                    mma_bf16(acc[i][j], all[i], bhh[j]);
                    mma_bf16(acc[i][j], ahh[i], bhh[j]);
                }
        }
        __syncthreads();
    }

#pragma unroll
    for (int i = 0; i < 2; i++)
#pragma unroll
        for (int half = 0; half < 2; half++) {
            int row = wm * 32 + i * 16 + half * 8 + g;
            float pout[NCLS];
#pragma unroll
            for (int c = 0; c < NCLS; c++) pout[c] = 0.f;
#pragma unroll
            for (int j = 0; j < 8; j++) {
                int col = wn * 64 + j * 8 + 2 * tg;
                float vA = (half ? acc[i][j].z : acc[i][j].x) + sb[col];
                float vB = (half ? acc[i][j].w : acc[i][j].y) + sb[col + 1];
                vA = 0.5f * vA * (1.f + erff(vA * 0.70710678118654752f));
                vB = 0.5f * vB * (1.f + erff(vB * 0.70710678118654752f));
#pragma unroll
                for (int c = 0; c < NCLS; c++)
                    pout[c] += vA * sw2[col][c] + vB * sw2[col + 1][c];
            }
#pragma unroll
            for (int c = 0; c < NCLS; c++) {
                pout[c] += __shfl_xor_sync(0xffffffffu, pout[c], 1);
                pout[c] += __shfl_xor_sync(0xffffffffu, pout[c], 2);
            }
            if (tg == 0) {
#pragma unroll
                for (int c = 0; c < NCLS; c++) atomicAdd(&s_out[row][c], pout[c]);
            }
        }
    __syncthreads();
    if (t < 128) {
        int p = row0 + t;
        if (p < EE2) {
            float4 o0, o1;
            o0.x = s_out[t][0] + mb2[0]; o0.y = s_out[t][1] + mb2[1];
            o0.z = s_out[t][2] + mb2[2]; o0.w = s_out[t][3] + mb2[3];
            o1.x = s_out[t][4] + mb2[4]; o1.y = s_out[t][5] + mb2[5];
            o1.z = s_out[t][6] + mb2[6]; o1.w = s_out[t][7] + mb2[7];
            *(float4*)&out[p * NCLS] = o0;
            *(float4*)&out[p * NCLS + 4] = o1;
        }
    }
}

// ---------------- launch (multi-stream fork/join, graph-capturable) ----------------
extern "C" void kernel_launch(void* const* d_in, const int* in_sizes, int n_in,
                              void* d_out, int out_size) {
    const float* x     = (const float*)d_in[0];
    const int*   ei    = (const int*)d_in[1];
    const int*   et    = (const int*)d_in[2];
    const int*   edges = (const int*)d_in[3];
    const float* w1 = (const float*)d_in[4];
    const float* q1 = (const float*)d_in[5];
    const float* k1 = (const float*)d_in[6];
    const float* b1 = (const float*)d_in[7];
    const float* w2 = (const float*)d_in[8];
    const float* q2 = (const float*)d_in[9];
    const float* k2 = (const float*)d_in[10];
    const float* b2 = (const float*)d_in[11];
    const float* ln1g = (const float*)d_in[12];
    const float* ln1b = (const float*)d_in[13];
    const float* ln2g = (const float*)d_in[14];
    const float* ln2b = (const float*)d_in[15];
    const float* mw1 = (const float*)d_in[16];
    const float* mb1 = (const float*)d_in[17];
    const float* mw2 = (const float*)d_in[18];
    const float* mb2 = (const float*)d_in[19];
    float* out = (float*)d_out;

    static cudaStream_t s1 = nullptr, s2 = nullptr;
    static cudaEvent_t evStart, evPrep, evW0, evFill, evA0, evH1, evA1;
    if (!s1) {
        cudaStreamCreateWithFlags(&s1, cudaStreamNonBlocking);
        cudaStreamCreateWithFlags(&s2, cudaStreamNonBlocking);
        cudaEventCreateWithFlags(&evStart, cudaEventDisableTiming);
        cudaEventCreateWithFlags(&evPrep,  cudaEventDisableTiming);
        cudaEventCreateWithFlags(&evW0,    cudaEventDisableTiming);
        cudaEventCreateWithFlags(&evFill,  cudaEventDisableTiming);
        cudaEventCreateWithFlags(&evA0,    cudaEventDisableTiming);
        cudaEventCreateWithFlags(&evH1,    cudaEventDisableTiming);
        cudaEventCreateWithFlags(&evA1,    cudaEventDisableTiming);
        cudaFuncSetAttribute(k_gemm16,  cudaFuncAttributeMaxDynamicSharedMemorySize, 3 * G_STAGE);
        cudaFuncSetAttribute(k_decode1, cudaFuncAttributeMaxDynamicSharedMemorySize, 2 * STAGE_BYTES);
    }

    const int prepTot = NN * HID / 4 + 2 * (RR * HID * HID / 4) + 2 * HID * HID / 4;
    const dim3 gXW((NN + 127) / 128, RR);

    cudaEventRecord(evStart, 0);
    cudaStreamWaitEvent(s1, evStart, 0);

    // side stream 1: wqk planes + CSR build
    k_wqk<<<(64 * HID + 255) / 256, 256, 0, s1>>>(w1, q1, k1, 0);
    cudaEventRecord(evW0, s1);
    k_wqk<<<(64 * HID + 255) / 256, 256, 0, s1>>>(w2, q2, k2, 1);
    k_zero<<<(NN + 255) / 256, 256, 0, s1>>>();
    k_hist<<<(EE + 255) / 256, 256, 0, s1>>>(ei);
    k_scan<<<1, 1024, 0, s1>>>();
    k_fill<<<(EE + 255) / 256, 256, 0, s1>>>(ei, et);
    cudaEventRecord(evFill, s1);

    // main: prep -> gemm(0)
    k_prep<<<(prepTot + 255) / 256, 256>>>(x, w1, w2, mw1);
    cudaEventRecord(evPrep, 0);

    cudaStreamWaitEvent(s2, evStart, 0);
    cudaStreamWaitEvent(s2, evPrep, 0);
    cudaStreamWaitEvent(s2, evW0, 0);
    k_aqk<<<(NN + 127) / 128, 256, 0, s2>>>(0);
    cudaEventRecord(evA0, s2);

    k_gemm16<<<gXW, 256, 3 * G_STAGE>>>(0);
    cudaStreamWaitEvent(0, evA0, 0);
    cudaStreamWaitEvent(0, evFill, 0);
    k_agg_ln<<<(NN + 7) / 8, 256>>>(b1, ln1g, ln1b, 1);
    cudaEventRecord(evH1, 0);

    cudaStreamWaitEvent(s2, evH1, 0);
    k_aqk<<<(NN + 127) / 128, 256, 0, s2>>>(1);
    cudaEventRecord(evA1, s2);

    k_gemm16<<<gXW, 256, 3 * G_STAGE>>>(1);
    cudaStreamWaitEvent(0, evA1, 0);
    k_agg_ln<<<(NN + 7) / 8, 256>>>(b2, ln2g, ln2b, 2);

    k_decode1<<<(EE2 + 127) / 128, 256, 2 * STAGE_BYTES>>>(edges, mb1, mw2, mb2, out);
}